// round 17
// baseline (speedup 1.0000x reference)
#include <cuda_runtime.h>
#include <cuda_bf16.h>
#include <math.h>

// out[j] = sum_{m=0}^{199} eigenvectors[l][m][n] * basis(m, x[j])
//   l==0: cos((pi/10)(m+0.5)x)   l>0: sin((pi/10)(m+1)x)
//
// R13: two kernels + PDL. Build tabulates F values over [-pi,pi] at G=4096
// intervals (16.4KB — half of R12): Catmull-Rom interp error budget allows it
// (h^4 scaling: ~1.2e-4 rel vs 1e-3 threshold). Eval copies table to shared
// (float4 fill, now 2x cheaper, occupancy cap lifted) and does 4 random LDS
// taps + cubic per point. Random LDS costs only bank-conflict degree (~4cyc)
// vs ~28 L1 wavefronts/warp for global gathers.

#define N_MAX    200
#define M_TERMS  200
#define GRID_G   4096               // intervals over [-pi, pi]
#define TABN     (GRID_G + 3)       // taps i-1..i+2 -> 1 front + 2 back guards
#define TABPAD   4100               // multiple of 4 for float4 fill
#define TBLOCK   256
#define EBLOCK   256

__device__ float g_table[TABPAD];

// ---------------- kernel 1: build value table ----------------
// g_table[k] = F(u_k), u_k = (k-1)*h - pi, h = 2*pi/GRID_G.
// Even/odd split: p_{m+2} = 2cos(2u) p_m - p_{m-2}; two 100-step chains.
__global__ __launch_bounds__(TBLOCK)
void build_table_kernel(const int* __restrict__ np,
                        const int* __restrict__ lp,
                        const float* __restrict__ eig)
{
    __shared__ float sc[M_TERMS];
    const int n = np[0];
    const int l = lp[0];
    const float* base = eig + (size_t)l * (N_MAX * N_MAX) + n;
    for (int m = threadIdx.x; m < M_TERMS; m += TBLOCK)
        sc[m] = base[(size_t)m * N_MAX];
    __syncthreads();

    const int g = blockIdx.x * TBLOCK + threadIdx.x;
    if (g < TABN) {
        const float u = (float)((double)(g - 1) * (6.283185307179586 / GRID_G)
                                - 3.141592653589793);
        float si, c;
        sincosf(u, &si, &c);
        const float c22 = fmaf(4.0f * c, c, -2.0f);   // 2cos(2u)

        float pe, pem, po, pom;
        if (l == 0) {
            float h0 = cosf(0.5f * u);
            pe  = h0;                    // p_0  = cos(u/2)
            pem = cosf(1.5f * u);        // p_{-2}= cos(-1.5u)
            po  = pem;                   // p_1  = cos(1.5u)
            pom = h0;                    // p_{-1}= cos(u/2)
        } else {
            pe  = si;                    // p_0  = sin(u)
            pem = -si;                   // p_{-2}= sin(-u)
            po  = 2.0f * si * c;         // p_1  = sin(2u)
            pom = 0.0f;                  // p_{-1}= sin(0)
        }

        float acce = 0.0f, acco = 0.0f;
        #pragma unroll 4
        for (int m = 0; m < M_TERMS; m += 2) {
            acce = fmaf(sc[m],     pe, acce);
            acco = fmaf(sc[m + 1], po, acco);
            float pne = fmaf(c22, pe, -pem);
            float pno = fmaf(c22, po, -pom);
            pem = pe; pe = pne;
            pom = po; po = pno;
        }
        g_table[g] = acce + acco;
    }
#if __CUDA_ARCH__ >= 900
    cudaTriggerProgrammaticLaunchCompletion();
#endif
}

// ---------------- kernel 2: evaluate from shared table ----------------
__device__ __forceinline__ float eval_one(const float* __restrict__ tab,
                                          float f, int i)
{
    float a = tab[i], b = tab[i + 1], c = tab[i + 2], d = tab[i + 3];
    // Catmull-Rom: b + 0.5f[(c-a)f + (2a-5b+4c-d)f^2 + (-a+3b-3c+d)f^3]
    float s1 = c - a;
    float t3 = fmaf(3.0f, b - c, d - a);      // -a+3b-3c+d
    float t2 = fmaf(-2.0f, b, a) + c - t3;    //  2a-5b+4c-d
    float h  = fmaf(f, t3, t2);
    h        = fmaf(f, h, s1);
    return fmaf(0.5f * f, h, b);
}

__global__ __launch_bounds__(EBLOCK)
void eval_kernel(const float4* __restrict__ x4,
                 float4* __restrict__ out4,
                 int N4,
                 const float* __restrict__ x,
                 float* __restrict__ out,
                 int N)
{
    __shared__ float tab[TABPAD];             // 16.4 KB static

    const float KG     = (float)GRID_G / 20.0f;   // 204.8
    const float CENTER = (float)(GRID_G / 2);     // 2048

    const int idx = blockIdx.x * EBLOCK + threadIdx.x;

    // --- pre-sync prologue: table-independent (hides under build via PDL) ---
    float4 xv = make_float4(0.f, 0.f, 0.f, 0.f);
    if (idx < N4) xv = __ldcs(&x4[idx]);

    float ti0 = fmaf(xv.x, KG, CENTER);
    float ti1 = fmaf(xv.y, KG, CENTER);
    float ti2 = fmaf(xv.z, KG, CENTER);
    float ti3 = fmaf(xv.w, KG, CENTER);
    int i0 = min(max((int)ti0, 0), GRID_G - 1);
    int i1 = min(max((int)ti1, 0), GRID_G - 1);
    int i2 = min(max((int)ti2, 0), GRID_G - 1);
    int i3 = min(max((int)ti3, 0), GRID_G - 1);
    float f0 = ti0 - (float)i0, f1 = ti1 - (float)i1;
    float f2 = ti2 - (float)i2, f3 = ti3 - (float)i3;

    float xr = 0.0f;
    int   kk = 0;
    bool  has_rem = (idx < (N & 3));
    if (has_rem) { kk = N4 * 4 + idx; xr = __ldcs(&x[kk]); }

#if __CUDA_ARCH__ >= 900
    cudaGridDependencySynchronize();          // table ready after this
#endif

    // cooperative fill: 1025 float4s (source becomes L1-resident per SM)
    {
        const float4* src = (const float4*)g_table;
        float4*       dst = (float4*)tab;
        #pragma unroll
        for (int k = threadIdx.x; k < TABPAD / 4; k += EBLOCK)
            dst[k] = __ldg(&src[k]);
    }
    __syncthreads();

    if (idx < N4) {
        float4 r;
        r.x = eval_one(tab, f0, i0);
        r.y = eval_one(tab, f1, i1);
        r.z = eval_one(tab, f2, i2);
        r.w = eval_one(tab, f3, i3);
        __stcs(&out4[idx], r);
    }
    if (has_rem) {
        float tv = fmaf(xr, KG, CENTER);
        int   ii = min(max((int)tv, 0), GRID_G - 1);
        out[kk]  = eval_one(tab, tv - (float)ii, ii);
    }
}

extern "C" void kernel_launch(void* const* d_in, const int* in_sizes, int n_in,
                              void* d_out, int out_size)
{
    const int*   n_p  = (const int*)d_in[0];
    const int*   l_p  = (const int*)d_in[1];
    const float* x    = (const float*)d_in[2];
    const float* eig  = (const float*)d_in[3];
    float*       out  = (float*)d_out;

    const int N  = in_sizes[2];
    const int N4 = N >> 2;

    const int tgrid = (TABN + TBLOCK - 1) / TBLOCK;   // 17 blocks
    build_table_kernel<<<tgrid, TBLOCK>>>(n_p, l_p, eig);

    const int egrid = (N4 + EBLOCK - 1) / EBLOCK;     // 977 blocks

    cudaLaunchConfig_t cfg = {};
    cfg.gridDim  = dim3((unsigned)egrid, 1, 1);
    cfg.blockDim = dim3(EBLOCK, 1, 1);
    cfg.dynamicSmemBytes = 0;
    cfg.stream = 0;
    cudaLaunchAttribute attr[1];
    attr[0].id = cudaLaunchAttributeProgrammaticStreamSerialization;
    attr[0].val.programmaticStreamSerializationAllowed = 1;
    cfg.attrs = attr;
    cfg.numAttrs = 1;

    cudaError_t e = cudaLaunchKernelEx(&cfg, eval_kernel,
                                       (const float4*)x, (float4*)out, N4,
                                       x, out, N);
    if (e != cudaSuccess) {
        eval_kernel<<<egrid, EBLOCK>>>((const float4*)x, (float4*)out, N4,
                                       x, out, N);
    }
}